// round 11
// baseline (speedup 1.0000x reference)
#include <cuda_runtime.h>
#include <cuda_bf16.h>

// SplineActivation: y[b][d] = sum_k Bspline_k(x[b][d]) * coeffs[d][k]
// Uniform cubic B-spline, branch-free truncated-power form:
//   t = 2x+2 in [0,4);  y(t) = P_0(t) + sum_{k=1..3} beta_k * ((t-k)+|t-k|)^3
// Width round: 256-bit global accesses (ld/st.global.v4.b64 — the only width
// sm_103a allows bare .L2::evict_* on). 8 dims per thread, f32x2 math on 4
// lane-pairs. Cuts LSU instruction count 4x vs the 64-bit version (STG.64
// issue cost 7.75cyc was a co-limiter) and natively encodes evict_last (x:
// 64MB, L2-resident) / evict_first (out: write-once drain) hints.
// Persistent 1-wave grid, 1-row-lookahead pipeline.

#define INPUT_DIM 4096
#define BATCH_N   4096
#define TPB       128
#define GRID_Y    148
#define DP8       (INPUT_DIM / 8)      // 512 column-octets per row

typedef unsigned long long u64;

__device__ __forceinline__ u64 pack2(float lo, float hi) {
    u64 r; asm("mov.b64 %0, {%1, %2};" : "=l"(r) : "f"(lo), "f"(hi)); return r;
}
__device__ __forceinline__ u64 fma2(u64 a, u64 b, u64 c) {
    u64 d; asm("fma.rn.f32x2 %0, %1, %2, %3;" : "=l"(d) : "l"(a), "l"(b), "l"(c)); return d;
}
__device__ __forceinline__ u64 mul2(u64 a, u64 b) {
    u64 d; asm("mul.rn.f32x2 %0, %1, %2;" : "=l"(d) : "l"(a), "l"(b)); return d;
}
__device__ __forceinline__ u64 add2(u64 a, u64 b) {
    u64 d; asm("add.rn.f32x2 %0, %1, %2;" : "=l"(d) : "l"(a), "l"(b)); return d;
}
__device__ __forceinline__ u64 abs2(u64 a) { return a & 0x7FFFFFFF7FFFFFFFULL; }

struct V4 { u64 a, b, c, d; };                     // 256-bit payload

__device__ __forceinline__ V4 ldg256_evl(const u64* p) {
    V4 v;
    asm volatile("ld.global.L2::evict_last.v4.b64 {%0, %1, %2, %3}, [%4];"
                 : "=l"(v.a), "=l"(v.b), "=l"(v.c), "=l"(v.d) : "l"(p));
    return v;
}
__device__ __forceinline__ void stg256_evf(u64* p, V4 v) {
    asm volatile("st.global.L2::evict_first.v4.b64 [%0], {%1, %2, %3, %4};"
                 :: "l"(p), "l"(v.a), "l"(v.b), "l"(v.c), "l"(v.d) : "memory");
}

struct PairPoly { u64 A, B, C, D, b1, b2, b3; };   // lanes = 2 dims

__device__ __forceinline__ u64 eval_pair(u64 x2, const PairPoly& q) {
    const u64 two2 = 0x4000000040000000ULL;   // {2,2}
    const u64 one2 = 0x3F8000003F800000ULL;   // {1,1}
    const u64 n1_2 = 0xBF800000BF800000ULL;   // {-1,-1}
    u64 t  = fma2(x2, two2, two2);            // 2x+2
    u64 r1 = fma2(x2, two2, one2);            // t-1
    u64 r2 = add2(x2, x2);                    // t-2
    u64 r3 = fma2(x2, two2, n1_2);            // t-3
    u64 p1 = add2(r1, abs2(r1));              // 2*(t-1)_+
    u64 p2 = add2(r2, abs2(r2));
    u64 p3 = add2(r3, abs2(r3));
    u64 h  = fma2(fma2(fma2(q.A, t, q.B), t, q.C), t, q.D);
    h = fma2(mul2(q.b1, p1), mul2(p1, p1), h);
    h = fma2(mul2(q.b2, p2), mul2(p2, p2), h);
    h = fma2(mul2(q.b3, p3), mul2(p3, p3), h);
    return h;
}

struct DimPoly { float A, B, C, D, b1, b2, b3; };

__device__ __forceinline__ float lead_coef(const float* e) {
    return fmaf(3.0f, e[1] - e[2], e[3] - e[0]);
}

__device__ __forceinline__ DimPoly build_dim(const float* e) {
    DimPoly q;
    float A0 = lead_coef(e + 0), A1 = lead_coef(e + 1);
    float A2 = lead_coef(e + 2), A3 = lead_coef(e + 3);
    q.A  = A0;
    q.B  = fmaf(-6.0f, e[1], 3.0f * (e[0] + e[2]));
    q.C  = 3.0f * (e[2] - e[0]);
    q.D  = fmaf(4.0f, e[1], e[0] + e[2]);
    q.b1 = (A1 - A0) * 0.125f;
    q.b2 = (A2 - A1) * 0.125f;
    q.b3 = (A3 - A2) * 0.125f;
    return q;
}

__global__ void __launch_bounds__(TPB)
spline_activation_kernel(const u64* __restrict__ x,
                         const float4* __restrict__ coeffs4,
                         u64* __restrict__ out) {
    int dq8 = blockIdx.x * TPB + threadIdx.x;        // 0..511 column-octet

    // 56 coeffs (8 dims x 7) = 14 x LDG.128 (224B*dq8 offset, 16B aligned).
    const float k6 = 1.0f / 6.0f;
    float c[56];
    const float4* cp = coeffs4 + (size_t)dq8 * 14;
#pragma unroll
    for (int i = 0; i < 14; ++i) {
        float4 v = __ldg(cp + i);
        c[4 * i + 0] = v.x * k6;
        c[4 * i + 1] = v.y * k6;
        c[4 * i + 2] = v.z * k6;
        c[4 * i + 3] = v.w * k6;
    }

    PairPoly q[4];
#pragma unroll
    for (int p = 0; p < 4; ++p) {
        DimPoly s0 = build_dim(c + 14 * p);
        DimPoly s1 = build_dim(c + 14 * p + 7);
        q[p].A  = pack2(s0.A,  s1.A);
        q[p].B  = pack2(s0.B,  s1.B);
        q[p].C  = pack2(s0.C,  s1.C);
        q[p].D  = pack2(s0.D,  s1.D);
        q[p].b1 = pack2(s0.b1, s1.b1);
        q[p].b2 = pack2(s0.b2, s1.b2);
        q[p].b3 = pack2(s0.b3, s1.b3);
    }

    // Persistent: rows r = blockIdx.y + GRID_Y * i.
    int row0 = blockIdx.y;
    int cnt  = (BATCH_N - row0 + GRID_Y - 1) / GRID_Y;     // 27 or 28
    const size_t ROW   = (size_t)DP8 * 4;                  // row stride in u64
    const size_t STEP  = (size_t)GRID_Y * ROW;
    size_t idx = (size_t)row0 * ROW + (size_t)dq8 * 4;     // u64 offset

    V4 cur = ldg256_evl(x + idx);
    for (int i = 0; i + 1 < cnt; ++i) {
        V4 nxt = ldg256_evl(x + idx + STEP);               // lookahead in flight
        V4 ov;
        ov.a = eval_pair(cur.a, q[0]);
        ov.b = eval_pair(cur.b, q[1]);
        ov.c = eval_pair(cur.c, q[2]);
        ov.d = eval_pair(cur.d, q[3]);
        stg256_evf(out + idx, ov);
        cur = nxt;
        idx += STEP;
    }
    {
        V4 ov;
        ov.a = eval_pair(cur.a, q[0]);
        ov.b = eval_pair(cur.b, q[1]);
        ov.c = eval_pair(cur.c, q[2]);
        ov.d = eval_pair(cur.d, q[3]);
        stg256_evf(out + idx, ov);
    }
}

extern "C" void kernel_launch(void* const* d_in, const int* in_sizes, int n_in,
                              void* d_out, int out_size) {
    const u64*    x      = (const u64*)d_in[0];      // (4096, 4096) fp32
    const float4* coeffs = (const float4*)d_in[1];   // (4096, 7) fp32
    u64*          out    = (u64*)d_out;              // (4096, 4096) fp32

    dim3 grid(DP8 / TPB, GRID_Y, 1);                 // (4, 148) = 592 CTAs
    spline_activation_kernel<<<grid, TPB>>>(x, coeffs, out);
}

// round 12
// speedup vs baseline: 1.1354x; 1.1354x over previous
#include <cuda_runtime.h>
#include <cuda_bf16.h>

// SplineActivation: y[b][d] = sum_k Bspline_k(x[b][d]) * coeffs[d][k]
// Uniform cubic B-spline, branch-free truncated-power form:
//   t = 2x+2 in [0,4);  y(t) = P_0(t) + sum_{k=1..3} beta_k * ((t-k)+|t-k|)^3
// Burst-phasing round: at 21.8us nothing is saturated (DRAM 48%, issue 52%,
// occ 55%) -> suspect HBM read/write turnaround losses from fine-grained
// R/W interleave. Batch 8 rows per stage: 2KB/warp pure-read burst, then
// 2KB/warp pure-write burst, coarsening the DRAM-visible phase granularity
// 4x vs the 1-row pipeline. Frame kept from R8/R10: 2 dims/thread f32x2
// (14 const regs), persistent 1-wave grid, __ldcg/__stcs policies.

#define INPUT_DIM 4096
#define BATCH_N   4096
#define TPB       128
#define GRID_Y    148
#define DP2       (INPUT_DIM / 2)      // 2048 column-pairs
#define RB        8                    // rows per read/write burst

typedef unsigned long long u64;

__device__ __forceinline__ u64 pack2(float lo, float hi) {
    u64 r; asm("mov.b64 %0, {%1, %2};" : "=l"(r) : "f"(lo), "f"(hi)); return r;
}
__device__ __forceinline__ u64 fma2(u64 a, u64 b, u64 c) {
    u64 d; asm("fma.rn.f32x2 %0, %1, %2, %3;" : "=l"(d) : "l"(a), "l"(b), "l"(c)); return d;
}
__device__ __forceinline__ u64 mul2(u64 a, u64 b) {
    u64 d; asm("mul.rn.f32x2 %0, %1, %2;" : "=l"(d) : "l"(a), "l"(b)); return d;
}
__device__ __forceinline__ u64 add2(u64 a, u64 b) {
    u64 d; asm("add.rn.f32x2 %0, %1, %2;" : "=l"(d) : "l"(a), "l"(b)); return d;
}
__device__ __forceinline__ u64 abs2(u64 a) { return a & 0x7FFFFFFF7FFFFFFFULL; }

struct PairPoly { u64 A, B, C, D, b1, b2, b3; };   // lanes = the 2 dims

__device__ __forceinline__ u64 eval_pair(u64 x2, const PairPoly& q) {
    const u64 two2 = 0x4000000040000000ULL;   // {2,2}
    const u64 one2 = 0x3F8000003F800000ULL;   // {1,1}
    const u64 n1_2 = 0xBF800000BF800000ULL;   // {-1,-1}
    u64 t  = fma2(x2, two2, two2);            // 2x+2
    u64 r1 = fma2(x2, two2, one2);            // t-1
    u64 r2 = add2(x2, x2);                    // t-2
    u64 r3 = fma2(x2, two2, n1_2);            // t-3
    u64 p1 = add2(r1, abs2(r1));              // 2*(t-1)_+
    u64 p2 = add2(r2, abs2(r2));
    u64 p3 = add2(r3, abs2(r3));
    u64 h  = fma2(fma2(fma2(q.A, t, q.B), t, q.C), t, q.D);
    h = fma2(mul2(q.b1, p1), mul2(p1, p1), h);
    h = fma2(mul2(q.b2, p2), mul2(p2, p2), h);
    h = fma2(mul2(q.b3, p3), mul2(p3, p3), h);
    return h;
}

struct DimPoly { float A, B, C, D, b1, b2, b3; };

__device__ __forceinline__ float lead_coef(const float* e) {
    return fmaf(3.0f, e[1] - e[2], e[3] - e[0]);
}

__device__ __forceinline__ DimPoly build_dim(const float* e) {
    DimPoly q;
    float A0 = lead_coef(e + 0), A1 = lead_coef(e + 1);
    float A2 = lead_coef(e + 2), A3 = lead_coef(e + 3);
    q.A  = A0;
    q.B  = fmaf(-6.0f, e[1], 3.0f * (e[0] + e[2]));
    q.C  = 3.0f * (e[2] - e[0]);
    q.D  = fmaf(4.0f, e[1], e[0] + e[2]);
    q.b1 = (A1 - A0) * 0.125f;
    q.b2 = (A2 - A1) * 0.125f;
    q.b3 = (A3 - A2) * 0.125f;
    return q;
}

__global__ void __launch_bounds__(TPB)
spline_activation_kernel(const u64* __restrict__ x,
                         const float2* __restrict__ coeffs2,
                         u64* __restrict__ out) {
    int dq2 = blockIdx.x * TPB + threadIdx.x;        // 0..2047 column-pair

    // 14 coeffs (2 dims x 7), 8B-aligned.
    const float k6 = 1.0f / 6.0f;
    float c[14];
    const float2* cp = coeffs2 + (size_t)dq2 * 7;
#pragma unroll
    for (int i = 0; i < 7; ++i) {
        float2 v = __ldg(cp + i);
        c[2 * i + 0] = v.x * k6;
        c[2 * i + 1] = v.y * k6;
    }
    DimPoly s0 = build_dim(c), s1 = build_dim(c + 7);
    PairPoly q;
    q.A  = pack2(s0.A,  s1.A);
    q.B  = pack2(s0.B,  s1.B);
    q.C  = pack2(s0.C,  s1.C);
    q.D  = pack2(s0.D,  s1.D);
    q.b1 = pack2(s0.b1, s1.b1);
    q.b2 = pack2(s0.b2, s1.b2);
    q.b3 = pack2(s0.b3, s1.b3);

    // Persistent: rows r = blockIdx.y + GRID_Y * i.
    int row0 = blockIdx.y;
    int cnt  = (BATCH_N - row0 + GRID_Y - 1) / GRID_Y;     // 27 or 28
    const size_t STEP = (size_t)GRID_Y * DP2;              // row stride (u64)
    size_t idx = (size_t)row0 * DP2 + dq2;

    int i = 0;
    for (; i + RB <= cnt; i += RB) {
        u64 a[RB];
        // pure read burst: 8 independent LDG.64 in flight (2KB/warp)
#pragma unroll
        for (int k = 0; k < RB; ++k)
            a[k] = __ldcg(x + idx + (size_t)k * STEP);
        // pure compute+write burst (2KB/warp)
#pragma unroll
        for (int k = 0; k < RB; ++k)
            __stcs(out + idx + (size_t)k * STEP, eval_pair(a[k], q));
        idx += (size_t)RB * STEP;
    }
    // tail (cnt = 27 -> 3 rows, cnt = 28 -> 4 rows)
    for (; i < cnt; ++i) {
        u64 a = __ldcg(x + idx);
        __stcs(out + idx, eval_pair(a, q));
        idx += STEP;
    }
}

extern "C" void kernel_launch(void* const* d_in, const int* in_sizes, int n_in,
                              void* d_out, int out_size) {
    const u64*    x      = (const u64*)d_in[0];      // (4096, 4096) fp32
    const float2* coeffs = (const float2*)d_in[1];   // (4096, 7) fp32
    u64*          out    = (u64*)d_out;              // (4096, 4096) fp32

    dim3 grid(DP2 / TPB, GRID_Y, 1);                 // (16, 148) = 2368 CTAs
    spline_activation_kernel<<<grid, TPB>>>(x, coeffs, out);
}